// round 8
// baseline (speedup 1.0000x reference)
#include <cuda_runtime.h>
#include <cuda_fp16.h>
#include <cstdint>

// Problem constants (fixed by the dataset)
#define NXc   1024          // input features (K)
#define NFc   4096          // output features (N)
#define BITSc 8             // bit planes
#define Gc    128           // NX/8 packed groups
#define Mc    4096          // tokens (2*2048)

#define BM 128
#define BN 128
#define BK 64               // k per chunk (4 k-steps of 16)
#define KC (NXc / BK)       // 16 k-chunks
#define STAGES 3
#define NT 1024             // total tiles (32 x 32)
#define GRID 304            // persistent CTAs (2 per SM, 152 SMs)

// Fragment-major fp16 tiles (uint32 = half2), 16KB each:
//   A tile: [mt(8)][ks(4)][lane(32)][4 u32]
//   B tile: [ntp(8)][ks(4)][lane(32)][4 u32]  (pair-interleaved: two n8 frags)
#define TILE_U32   4096
#define TILE_BYTES 16384

__device__ uint32_t g_Xt[(size_t)Mc * NXc / 2];   // [m_blk(32)][kc(16)][TILE]
__device__ uint32_t g_Wt[(size_t)NFc * NXc / 2];  // [n_blk(32)][kc(16)][TILE]

// ---------------------------------------------------------------------------
__device__ __forceinline__ uint32_t smem_u32(const void* p) {
    uint32_t a;
    asm("{ .reg .u64 t; cvta.to.shared.u64 t, %1; cvt.u32.u64 %0, t; }" : "=r"(a) : "l"(p));
    return a;
}
__device__ __forceinline__ void cp_async16(uint32_t saddr, const void* gaddr) {
    asm volatile("cp.async.cg.shared.global [%0], [%1], 16;" :: "r"(saddr), "l"(gaddr) : "memory");
}
__device__ __forceinline__ void cp_commit() {
    asm volatile("cp.async.commit_group;" ::: "memory");
}
template <int N>
__device__ __forceinline__ void cp_wait() {
    asm volatile("cp.async.wait_group %0;" :: "n"(N) : "memory");
}
__device__ __forceinline__ uint32_t pack_h2(float lo, float hi) {
    __half2 h = __floats2half2_rn(lo, hi);   // lo -> low 16 bits
    return *reinterpret_cast<uint32_t*>(&h);
}
__device__ __forceinline__ void mma_f16(float* d, const uint32_t* a, const uint32_t* b) {
    asm volatile(
        "mma.sync.aligned.m16n8k16.row.col.f32.f16.f16.f32 "
        "{%0,%1,%2,%3}, {%4,%5,%6,%7}, {%8,%9}, {%0,%1,%2,%3};"
        : "+f"(d[0]), "+f"(d[1]), "+f"(d[2]), "+f"(d[3])
        : "r"(a[0]), "r"(a[1]), "r"(a[2]), "r"(a[3]), "r"(b[0]), "r"(b[1]));
}

// ---------------------------------------------------------------------------
// Fused prep kernel: blocks [0,1024) decode W; blocks [1024,3072) repack x.
// ---------------------------------------------------------------------------
__global__ void __launch_bounds__(256)
prep_kernel(const int* __restrict__ binary, const float* __restrict__ scale,
            const float* __restrict__ x) {
    if (blockIdx.x < 1024) {
        // ---- decode: packed signs -> W, pair-interleaved fp16 B layout ----
        int tid = blockIdx.x * 256 + threadIdx.x;   // NF * G/2 threads
        int f  = tid >> 6;
        int gp = tid & 63;

        float w[16];
#pragma unroll
        for (int j = 0; j < 16; j++) w[j] = 0.0f;
#pragma unroll
        for (int k = 0; k < BITSc; k++) {
            int2 bb = *reinterpret_cast<const int2*>(
                binary + (size_t)(k * NFc + f) * Gc + 2 * gp);
            float s = __ldg(scale + k * NFc + f);
#pragma unroll
            for (int j = 0; j < 8; j++) {
                w[j]     += ((bb.x >> (7 - j)) & 1) ? s : -s;
                w[8 + j] += ((bb.y >> (7 - j)) & 1) ? s : -s;
            }
        }

        int n_blk = f >> 7;
        int nt    = (f & 127) >> 3;    // 0..15
        int ntp   = nt >> 1;           // pair index 0..7
        int half  = nt & 1;            // low/high half of the uint4
        int col   = f & 7;
        int kc    = gp >> 2;           // k-chunk (BK=64)
        int ks    = gp & 3;            // k16-step within chunk

        uint32_t* tile = g_Wt + (size_t)(n_blk * KC + kc) * TILE_U32;
#pragma unroll
        for (int c = 0; c < 4; c++) {
            uint2 v;
            v.x = pack_h2(w[2 * c], w[2 * c + 1]);          // reg b0
            v.y = pack_h2(w[8 + 2 * c], w[9 + 2 * c]);      // reg b1
            *reinterpret_cast<uint2*>(
                tile + ((ntp * 4 + ks) * 32 + col * 4 + c) * 4 + half * 2) = v;
        }
    } else {
        // ---- repack: x -> fragment-major fp16 A layout ----
        int tid  = (blockIdx.x - 1024) * 256 + threadIdx.x;  // M*K/8 threads
        int lane = tid & 31;
        int ks   = (tid >> 5) & 3;
        int mt   = (tid >> 7) & 7;
        int kc   = (tid >> 10) & (KC - 1);
        int mblk = tid >> 14;

        int row = mblk * BM + mt * 16 + (lane >> 2);
        int k0  = kc * BK + ks * 16 + (lane & 3) * 2;

        const float* r0 = x + (size_t)row * NXc;
        const float* r1 = r0 + 8 * NXc;

        float2 p00 = *reinterpret_cast<const float2*>(r0 + k0);
        float2 p10 = *reinterpret_cast<const float2*>(r1 + k0);
        float2 p01 = *reinterpret_cast<const float2*>(r0 + k0 + 8);
        float2 p11 = *reinterpret_cast<const float2*>(r1 + k0 + 8);

        uint4 v;
        v.x = pack_h2(p00.x, p00.y);
        v.y = pack_h2(p10.x, p10.y);
        v.z = pack_h2(p01.x, p01.y);
        v.w = pack_h2(p11.x, p11.y);

        uint32_t* tile = g_Xt + (size_t)(mblk * KC + kc) * TILE_U32;
        *reinterpret_cast<uint4*>(tile + ((mt * 4 + ks) * 32 + lane) * 4) = v;
    }
}

// ---------------------------------------------------------------------------
// Persistent fp16 mma.sync GEMM. 128x128 tiles, 256 threads (8 warps, 2m x 4n,
// warp tile 64x32), continuous 3-stage cp.async pipeline across tiles.
// ONE __syncthreads per chunk; per-warp staggered ks order to spread the
// post-barrier LDS burst across the smem crossbar.
// ---------------------------------------------------------------------------
#define SMEM_TOTAL (STAGES * 2 * TILE_BYTES)   // 96 KB

__global__ void __launch_bounds__(256)
gemm_kernel(const float* __restrict__ bias, float* __restrict__ out) {
    extern __shared__ uint32_t smem[];
    uint32_t* sA = smem;                          // [STAGES][TILE_U32]
    uint32_t* sB = smem + STAGES * TILE_U32;      // [STAGES][TILE_U32]
    const uint32_t sA0 = smem_u32(sA);
    const uint32_t sB0 = smem_u32(sB);

    const int tid  = threadIdx.x;
    const int lane = tid & 31;
    const int wid  = tid >> 5;
    const int wm   = wid >> 2;      // 0..1
    const int wn   = wid & 3;       // 0..3
    const int kofs = wid & 3;       // per-warp ks stagger
    const int bid  = blockIdx.x;

    const int n_my = (NT - bid + GRID - 1) / GRID;   // tiles for this CTA
    const int Q    = n_my * KC;                      // flat chunk count

    // issue prefetch of flat chunk q into stage q%STAGES (always commits)
    auto prefetch = [&](int q) {
        if (q < Q) {
            const int t = bid + (q >> 4) * GRID;     // tile id
            const int c = q & 15;                    // k-chunk
            const char* Ag = (const char*)(g_Xt +
                ((size_t)(t >> 5) * KC + c) * TILE_U32);
            const char* Bg = (const char*)(g_Wt +
                ((size_t)(t & 31) * KC + c) * TILE_U32);
            const int s = q % STAGES;
#pragma unroll
            for (int i = 0; i < 4; i++) {
                cp_async16(sA0 + s * TILE_BYTES + i * 4096 + tid * 16,
                           Ag + i * 4096 + tid * 16);
                cp_async16(sB0 + s * TILE_BYTES + i * 4096 + tid * 16,
                           Bg + i * 4096 + tid * 16);
            }
        }
        cp_commit();
    };

    float acc[4][4][4];
#pragma unroll
    for (int i = 0; i < 4; i++)
#pragma unroll
        for (int j = 0; j < 4; j++)
#pragma unroll
            for (int r = 0; r < 4; r++) acc[i][j][r] = 0.0f;

    prefetch(0);
    prefetch(1);

    for (int q = 0; q < Q; q++) {
        cp_wait<STAGES - 2>();
        __syncthreads();          // single rendezvous per chunk

        prefetch(q + 2);

        const uint32_t* A = sA + (q % STAGES) * TILE_U32;
        const uint32_t* B = sB + (q % STAGES) * TILE_U32;

#pragma unroll
        for (int kk = 0; kk < 4; kk++) {
            const int ks = (kk + kofs) & 3;   // staggered per warp
            uint32_t a[4][4], b[4][2];
#pragma unroll
            for (int i = 0; i < 4; i++) {
                uint4 v = *reinterpret_cast<const uint4*>(
                    A + (((wm * 4 + i) * 4 + ks) * 32 + lane) * 4);
                a[i][0] = v.x; a[i][1] = v.y; a[i][2] = v.z; a[i][3] = v.w;
            }
#pragma unroll
            for (int jp = 0; jp < 2; jp++) {
                uint4 v = *reinterpret_cast<const uint4*>(
                    B + (((wn * 2 + jp) * 4 + ks) * 32 + lane) * 4);
                b[2 * jp][0]     = v.x; b[2 * jp][1]     = v.y;
                b[2 * jp + 1][0] = v.z; b[2 * jp + 1][1] = v.w;
            }
#pragma unroll
            for (int i = 0; i < 4; i++)
#pragma unroll
                for (int j = 0; j < 4; j++)
                    mma_f16(acc[i][j], a[i], b[j]);
        }

        if ((q & 15) == 15) {
            // epilogue for the tile just finished
            const int t     = bid + (q >> 4) * GRID;
            const int row0  = (t >> 5) * BM + wm * 64 + (lane >> 2);
            const int col0  = (t & 31) * BN + wn * 32 + (lane & 3) * 2;
#pragma unroll
            for (int j = 0; j < 4; j++) {
                const int n = col0 + j * 8;
                const float2 bv = *reinterpret_cast<const float2*>(bias + n);
#pragma unroll
                for (int i = 0; i < 4; i++) {
                    const int m = row0 + i * 16;
                    float2 v0, v1;
                    v0.x = acc[i][j][0] + bv.x;
                    v0.y = acc[i][j][1] + bv.y;
                    v1.x = acc[i][j][2] + bv.x;
                    v1.y = acc[i][j][3] + bv.y;
                    *reinterpret_cast<float2*>(out + (size_t)m * NFc + n)       = v0;
                    *reinterpret_cast<float2*>(out + (size_t)(m + 8) * NFc + n) = v1;
                }
            }
#pragma unroll
            for (int i = 0; i < 4; i++)
#pragma unroll
                for (int j = 0; j < 4; j++)
#pragma unroll
                    for (int r = 0; r < 4; r++) acc[i][j][r] = 0.0f;
        }
    }
}

// ---------------------------------------------------------------------------
// Launch
// ---------------------------------------------------------------------------
extern "C" void kernel_launch(void* const* d_in, const int* in_sizes, int n_in,
                              void* d_out, int out_size) {
    const float* x      = (const float*)d_in[0];
    const int*   binary = (const int*)  d_in[1];
    const float* scale  = (const float*)d_in[2];
    const float* bias   = (const float*)d_in[3];
    float*       out    = (float*)d_out;

    cudaFuncSetAttribute(gemm_kernel,
                         cudaFuncAttributeMaxDynamicSharedMemorySize, SMEM_TOTAL);

    prep_kernel<<<3072, 256>>>(binary, scale, x);
    gemm_kernel<<<GRID, 256, SMEM_TOTAL>>>(bias, out);
}

// round 9
// speedup vs baseline: 1.0218x; 1.0218x over previous
#include <cuda_runtime.h>
#include <cuda_fp16.h>
#include <cstdint>

// Problem constants (fixed by the dataset)
#define NXc   1024          // input features (K)
#define NFc   4096          // output features (N)
#define BITSc 8             // bit planes
#define Gc    128           // NX/8 packed groups
#define Mc    4096          // tokens (2*2048)

#define BM 128
#define BN 128
#define BK 64               // k per chunk (4 k-steps of 16)
#define KC (NXc / BK)       // 16 k-chunks
#define STAGES 3

// Tile = 16KB in fragment-major fp16 layout (uint32 = half2):
//   A tile: [mt(8)][ks(4)][lane(32)][4 regs]  = 4096 u32
//   B tile: [nt(16)][ks(4)][lane(32)][2 regs] = 4096 u32
#define TILE_U32   4096
#define TILE_BYTES 16384

__device__ uint32_t g_Xt[(size_t)Mc * NXc / 2];   // [m_blk(32)][kc(16)][TILE]
__device__ uint32_t g_Wt[(size_t)NFc * NXc / 2];  // [n_blk(32)][kc(16)][TILE]

// ---------------------------------------------------------------------------
__device__ __forceinline__ uint32_t smem_u32(const void* p) {
    uint32_t a;
    asm("{ .reg .u64 t; cvta.to.shared.u64 t, %1; cvt.u32.u64 %0, t; }" : "=r"(a) : "l"(p));
    return a;
}
__device__ __forceinline__ void cp_async16(uint32_t saddr, const void* gaddr) {
    asm volatile("cp.async.cg.shared.global [%0], [%1], 16;" :: "r"(saddr), "l"(gaddr) : "memory");
}
__device__ __forceinline__ void cp_commit() {
    asm volatile("cp.async.commit_group;" ::: "memory");
}
template <int N>
__device__ __forceinline__ void cp_wait() {
    asm volatile("cp.async.wait_group %0;" :: "n"(N) : "memory");
}
__device__ __forceinline__ uint32_t pack_h2(float lo, float hi) {
    __half2 h = __floats2half2_rn(lo, hi);   // lo -> low 16 bits
    return *reinterpret_cast<uint32_t*>(&h);
}
__device__ __forceinline__ void mma_f16(float* d, const uint32_t* a, const uint32_t* b) {
    asm volatile(
        "mma.sync.aligned.m16n8k16.row.col.f32.f16.f16.f32 "
        "{%0,%1,%2,%3}, {%4,%5,%6,%7}, {%8,%9}, {%0,%1,%2,%3};"
        : "+f"(d[0]), "+f"(d[1]), "+f"(d[2]), "+f"(d[3])
        : "r"(a[0]), "r"(a[1]), "r"(a[2]), "r"(a[3]), "r"(b[0]), "r"(b[1]));
}

// ---------------------------------------------------------------------------
// Fused prep kernel: blocks [0,1024) decode W; blocks [1024,3072) repack x.
// Layouts identical to the proven R4 kernels.
// ---------------------------------------------------------------------------
__global__ void __launch_bounds__(256)
prep_kernel(const int* __restrict__ binary, const float* __restrict__ scale,
            const float* __restrict__ x) {
    if (blockIdx.x < 1024) {
        // ---- decode: packed signs -> W, fragment-major fp16 B layout ----
        int tid = blockIdx.x * 256 + threadIdx.x;   // NF * G/2 threads
        int f  = tid >> 6;
        int gp = tid & 63;

        float w[16];
#pragma unroll
        for (int j = 0; j < 16; j++) w[j] = 0.0f;
#pragma unroll
        for (int k = 0; k < BITSc; k++) {
            int2 bb = *reinterpret_cast<const int2*>(
                binary + (size_t)(k * NFc + f) * Gc + 2 * gp);
            float s = __ldg(scale + k * NFc + f);
#pragma unroll
            for (int j = 0; j < 8; j++) {
                w[j]     += ((bb.x >> (7 - j)) & 1) ? s : -s;
                w[8 + j] += ((bb.y >> (7 - j)) & 1) ? s : -s;
            }
        }

        int n_blk = f >> 7;
        int nt    = (f & 127) >> 3;
        int col   = f & 7;
        int kc    = gp >> 2;           // k-chunk (BK=64)
        int ks    = gp & 3;            // k16-step within chunk

        uint32_t* tile = g_Wt + (size_t)(n_blk * KC + kc) * TILE_U32;
        uint32_t* base = tile + ((nt * 4 + ks) * 32 + col * 4) * 2;
#pragma unroll
        for (int c = 0; c < 4; c++) {
            uint2 v;
            v.x = pack_h2(w[2 * c], w[2 * c + 1]);
            v.y = pack_h2(w[8 + 2 * c], w[9 + 2 * c]);
            *reinterpret_cast<uint2*>(base + c * 2) = v;
        }
    } else {
        // ---- repack: x -> fragment-major fp16 A layout ----
        int tid  = (blockIdx.x - 1024) * 256 + threadIdx.x;  // M*K/8 threads
        int lane = tid & 31;
        int ks   = (tid >> 5) & 3;
        int mt   = (tid >> 7) & 7;
        int kc   = (tid >> 10) & (KC - 1);
        int mblk = tid >> 14;

        int row = mblk * BM + mt * 16 + (lane >> 2);
        int k0  = kc * BK + ks * 16 + (lane & 3) * 2;

        const float* r0 = x + (size_t)row * NXc;
        const float* r1 = r0 + 8 * NXc;

        float2 p00 = *reinterpret_cast<const float2*>(r0 + k0);
        float2 p10 = *reinterpret_cast<const float2*>(r1 + k0);
        float2 p01 = *reinterpret_cast<const float2*>(r0 + k0 + 8);
        float2 p11 = *reinterpret_cast<const float2*>(r1 + k0 + 8);

        uint4 v;
        v.x = pack_h2(p00.x, p00.y);
        v.y = pack_h2(p10.x, p10.y);
        v.z = pack_h2(p01.x, p01.y);
        v.w = pack_h2(p11.x, p11.y);

        uint32_t* tile = g_Xt + (size_t)(mblk * BM / 128 * KC + kc) * TILE_U32;
        *reinterpret_cast<uint4*>(tile + ((mt * 4 + ks) * 32 + lane) * 4) = v;
    }
}

// ---------------------------------------------------------------------------
// Kernel 3: fp16 mma.sync GEMM (R4 trunk). 128x128 tile, 256 threads
// (8 warps, 2m x 4n, warp tile 64x32), 3-stage cp.async, two syncs/chunk.
// R9 deltas: chunk prefetch issued AFTER ks=0 fragment loads; A fragments
// double-buffered across ks.
// ---------------------------------------------------------------------------
#define SMEM_TOTAL (STAGES * 2 * TILE_BYTES)   // 96 KB

__global__ void __launch_bounds__(256)
gemm_kernel(const float* __restrict__ bias, float* __restrict__ out) {
    extern __shared__ uint32_t smem[];
    uint32_t* sA = smem;                          // [STAGES][TILE_U32]
    uint32_t* sB = smem + STAGES * TILE_U32;      // [STAGES][TILE_U32]
    const uint32_t sA0 = smem_u32(sA);
    const uint32_t sB0 = smem_u32(sB);

    const int tid  = threadIdx.x;
    const int lane = tid & 31;
    const int wid  = tid >> 5;
    const int wm   = wid >> 2;      // 0..1
    const int wn   = wid & 3;       // 0..3
    const int n_blk = blockIdx.x;
    const int m_blk = blockIdx.y;

    const char* Ag = (const char*)(g_Xt + (size_t)m_blk * KC * TILE_U32);
    const char* Bg = (const char*)(g_Wt + (size_t)n_blk * KC * TILE_U32);

    float acc[4][4][4];
#pragma unroll
    for (int i = 0; i < 4; i++)
#pragma unroll
        for (int j = 0; j < 4; j++)
#pragma unroll
            for (int r = 0; r < 4; r++) acc[i][j][r] = 0.0f;

    // prefetch stages 0..STAGES-2 (4 x 16B per tile per thread)
#pragma unroll
    for (int c = 0; c < STAGES - 1; c++) {
#pragma unroll
        for (int i = 0; i < 4; i++) {
            cp_async16(sA0 + c * TILE_BYTES + i * 4096 + tid * 16,
                       Ag + (size_t)c * TILE_BYTES + i * 4096 + tid * 16);
            cp_async16(sB0 + c * TILE_BYTES + i * 4096 + tid * 16,
                       Bg + (size_t)c * TILE_BYTES + i * 4096 + tid * 16);
        }
        cp_commit();
    }

    uint32_t a[2][4][4];

    for (int c = 0; c < KC; c++) {
        cp_wait<STAGES - 2>();
        __syncthreads();

        const uint32_t* A = sA + (c % STAGES) * TILE_U32;
        const uint32_t* B = sB + (c % STAGES) * TILE_U32;

        // ks=0 A fragments FIRST so MMAs can start ASAP
#pragma unroll
        for (int i = 0; i < 4; i++) {
            uint4 v = *reinterpret_cast<const uint4*>(
                A + (((wm * 4 + i) * 4 + 0) * 32 + lane) * 4);
            a[0][i][0] = v.x; a[0][i][1] = v.y; a[0][i][2] = v.z; a[0][i][3] = v.w;
        }

        // chunk prefetch AFTER the critical fragment loads
        int cp = c + STAGES - 1;
        if (cp < KC) {
            int s = cp % STAGES;
#pragma unroll
            for (int i = 0; i < 4; i++) {
                cp_async16(sA0 + s * TILE_BYTES + i * 4096 + tid * 16,
                           Ag + (size_t)cp * TILE_BYTES + i * 4096 + tid * 16);
                cp_async16(sB0 + s * TILE_BYTES + i * 4096 + tid * 16,
                           Bg + (size_t)cp * TILE_BYTES + i * 4096 + tid * 16);
            }
        }
        cp_commit();

#pragma unroll
        for (int ks = 0; ks < 4; ks++) {
            const int cur = ks & 1, nxt = cur ^ 1;
            // prefetch next ks A fragments (overlaps this ks's MMA burst)
            if (ks < 3) {
#pragma unroll
                for (int i = 0; i < 4; i++) {
                    uint4 v = *reinterpret_cast<const uint4*>(
                        A + (((wm * 4 + i) * 4 + ks + 1) * 32 + lane) * 4);
                    a[nxt][i][0] = v.x; a[nxt][i][1] = v.y;
                    a[nxt][i][2] = v.z; a[nxt][i][3] = v.w;
                }
            }
            uint32_t b[4][2];
#pragma unroll
            for (int j = 0; j < 4; j++) {
                uint2 v = *reinterpret_cast<const uint2*>(
                    B + (((wn * 4 + j) * 4 + ks) * 32 + lane) * 2);
                b[j][0] = v.x; b[j][1] = v.y;
            }
#pragma unroll
            for (int i = 0; i < 4; i++)
#pragma unroll
                for (int j = 0; j < 4; j++)
                    mma_f16(acc[i][j], a[cur][i], b[j]);
        }
        __syncthreads();
    }

    // epilogue: c0,c1 at (row, col/col+1); c2,c3 at (row+8, ·)
    const int row0 = m_blk * BM + wm * 64 + (lane >> 2);
    const int col0 = n_blk * BN + wn * 32 + (lane & 3) * 2;
#pragma unroll
    for (int j = 0; j < 4; j++) {
        const int n = col0 + j * 8;
        const float2 bv = *reinterpret_cast<const float2*>(bias + n);
#pragma unroll
        for (int i = 0; i < 4; i++) {
            const int m = row0 + i * 16;
            float2 v0, v1;
            v0.x = acc[i][j][0] + bv.x;
            v0.y = acc[i][j][1] + bv.y;
            v1.x = acc[i][j][2] + bv.x;
            v1.y = acc[i][j][3] + bv.y;
            *reinterpret_cast<float2*>(out + (size_t)m * NFc + n)       = v0;
            *reinterpret_cast<float2*>(out + (size_t)(m + 8) * NFc + n) = v1;
        }
    }
}

// ---------------------------------------------------------------------------
// Launch
// ---------------------------------------------------------------------------
extern "C" void kernel_launch(void* const* d_in, const int* in_sizes, int n_in,
                              void* d_out, int out_size) {
    const float* x      = (const float*)d_in[0];
    const int*   binary = (const int*)  d_in[1];
    const float* scale  = (const float*)d_in[2];
    const float* bias   = (const float*)d_in[3];
    float*       out    = (float*)d_out;

    cudaFuncSetAttribute(gemm_kernel,
                         cudaFuncAttributeMaxDynamicSharedMemorySize, SMEM_TOTAL);

    prep_kernel<<<3072, 256>>>(binary, scale, x);

    dim3 grid(NFc / BN, Mc / BM);      // 32 x 32
    gemm_kernel<<<grid, 256, SMEM_TOTAL>>>(bias, out);
}

// round 10
// speedup vs baseline: 1.0635x; 1.0408x over previous
#include <cuda_runtime.h>
#include <cuda_fp16.h>
#include <cstdint>

// Problem constants (fixed by the dataset)
#define NXc   1024          // input features (K)
#define NFc   4096          // output features (N)
#define BITSc 8             // bit planes
#define Gc    128           // NX/8 packed groups
#define Mc    4096          // tokens (2*2048)

#define BM 128
#define BN 128
#define BK 64               // k per chunk (4 k-steps of 16)
#define KC (NXc / BK)       // 16 k-chunks
#define STAGES 3

// Fragment-major fp16 tiles (uint32 = half2), 16KB each:
//   A tile: [mt(8)][ks(4)][lane(32)][4 regs]  = 4096 u32
//   B tile: [nt(16)][ks(4)][lane(32)][2 regs] = 4096 u32   (read via LDG)
#define TILE_U32   4096
#define TILE_BYTES 16384

__device__ uint32_t g_Xt[(size_t)Mc * NXc / 2];   // [m_blk(32)][kc(16)][TILE]
__device__ uint32_t g_Wt[(size_t)NFc * NXc / 2];  // [n_blk(32)][kc(16)][TILE]

// ---------------------------------------------------------------------------
__device__ __forceinline__ uint32_t smem_u32(const void* p) {
    uint32_t a;
    asm("{ .reg .u64 t; cvta.to.shared.u64 t, %1; cvt.u32.u64 %0, t; }" : "=r"(a) : "l"(p));
    return a;
}
__device__ __forceinline__ void cp_async16(uint32_t saddr, const void* gaddr) {
    asm volatile("cp.async.cg.shared.global [%0], [%1], 16;" :: "r"(saddr), "l"(gaddr) : "memory");
}
__device__ __forceinline__ void cp_commit() {
    asm volatile("cp.async.commit_group;" ::: "memory");
}
template <int N>
__device__ __forceinline__ void cp_wait() {
    asm volatile("cp.async.wait_group %0;" :: "n"(N) : "memory");
}
__device__ __forceinline__ uint32_t pack_h2(float lo, float hi) {
    __half2 h = __floats2half2_rn(lo, hi);   // lo -> low 16 bits
    return *reinterpret_cast<uint32_t*>(&h);
}
__device__ __forceinline__ void mma_f16(float* d, const uint32_t* a, const uint32_t* b) {
    asm volatile(
        "mma.sync.aligned.m16n8k16.row.col.f32.f16.f16.f32 "
        "{%0,%1,%2,%3}, {%4,%5,%6,%7}, {%8,%9}, {%0,%1,%2,%3};"
        : "+f"(d[0]), "+f"(d[1]), "+f"(d[2]), "+f"(d[3])
        : "r"(a[0]), "r"(a[1]), "r"(a[2]), "r"(a[3]), "r"(b[0]), "r"(b[1]));
}

// ---------------------------------------------------------------------------
// Fused prep kernel: blocks [0,1024) decode W; blocks [1024,3072) repack x.
// Layouts identical to the proven R4 kernels.
// ---------------------------------------------------------------------------
__global__ void __launch_bounds__(256)
prep_kernel(const int* __restrict__ binary, const float* __restrict__ scale,
            const float* __restrict__ x) {
    if (blockIdx.x < 1024) {
        // ---- decode: packed signs -> W, fragment-major fp16 B layout ----
        int tid = blockIdx.x * 256 + threadIdx.x;   // NF * G/2 threads
        int f  = tid >> 6;
        int gp = tid & 63;

        float w[16];
#pragma unroll
        for (int j = 0; j < 16; j++) w[j] = 0.0f;
#pragma unroll
        for (int k = 0; k < BITSc; k++) {
            int2 bb = *reinterpret_cast<const int2*>(
                binary + (size_t)(k * NFc + f) * Gc + 2 * gp);
            float s = __ldg(scale + k * NFc + f);
#pragma unroll
            for (int j = 0; j < 8; j++) {
                w[j]     += ((bb.x >> (7 - j)) & 1) ? s : -s;
                w[8 + j] += ((bb.y >> (7 - j)) & 1) ? s : -s;
            }
        }

        int n_blk = f >> 7;
        int nt    = (f & 127) >> 3;
        int col   = f & 7;
        int kc    = gp >> 2;           // k-chunk (BK=64)
        int ks    = gp & 3;            // k16-step within chunk

        uint32_t* tile = g_Wt + (size_t)(n_blk * KC + kc) * TILE_U32;
        uint32_t* base = tile + ((nt * 4 + ks) * 32 + col * 4) * 2;
#pragma unroll
        for (int c = 0; c < 4; c++) {
            uint2 v;
            v.x = pack_h2(w[2 * c], w[2 * c + 1]);
            v.y = pack_h2(w[8 + 2 * c], w[9 + 2 * c]);
            *reinterpret_cast<uint2*>(base + c * 2) = v;
        }
    } else {
        // ---- repack: x -> fragment-major fp16 A layout ----
        int tid  = (blockIdx.x - 1024) * 256 + threadIdx.x;  // M*K/8 threads
        int lane = tid & 31;
        int ks   = (tid >> 5) & 3;
        int mt   = (tid >> 7) & 7;
        int kc   = (tid >> 10) & (KC - 1);
        int mblk = tid >> 14;

        int row = mblk * BM + mt * 16 + (lane >> 2);
        int k0  = kc * BK + ks * 16 + (lane & 3) * 2;

        const float* r0 = x + (size_t)row * NXc;
        const float* r1 = r0 + 8 * NXc;

        float2 p00 = *reinterpret_cast<const float2*>(r0 + k0);
        float2 p10 = *reinterpret_cast<const float2*>(r1 + k0);
        float2 p01 = *reinterpret_cast<const float2*>(r0 + k0 + 8);
        float2 p11 = *reinterpret_cast<const float2*>(r1 + k0 + 8);

        uint4 v;
        v.x = pack_h2(p00.x, p00.y);
        v.y = pack_h2(p10.x, p10.y);
        v.z = pack_h2(p01.x, p01.y);
        v.w = pack_h2(p11.x, p11.y);

        uint32_t* tile = g_Xt + (size_t)(mblk * KC + kc) * TILE_U32;
        *reinterpret_cast<uint4*>(tile + ((mt * 4 + ks) * 32 + lane) * 4) = v;
    }
}

// ---------------------------------------------------------------------------
// GEMM: fp16 mma.sync, 128x128 tile, 256 threads (8 warps, 2m x 4n, warp
// tile 64x32), 3-stage cp.async for A ONLY; B fragments stream straight
// from global (L1/L2) into registers, ks-double-buffered. This removes B's
// STS+LDS from the smem crossbar, which R9 profiling showed was exactly
// co-saturated with the tensor pipe.
// ---------------------------------------------------------------------------
#define SMEM_TOTAL (STAGES * TILE_BYTES)   // 48 KB (A stages only)

__global__ void __launch_bounds__(256, 2)
gemm_kernel(const float* __restrict__ bias, float* __restrict__ out) {
    extern __shared__ uint32_t smem[];
    uint32_t* sA = smem;                          // [STAGES][TILE_U32]
    const uint32_t sA0 = smem_u32(sA);

    const int tid  = threadIdx.x;
    const int lane = tid & 31;
    const int wid  = tid >> 5;
    const int wm   = wid >> 2;      // 0..1
    const int wn   = wid & 3;       // 0..3
    const int n_blk = blockIdx.x;
    const int m_blk = blockIdx.y;

    const char* Ag = (const char*)(g_Xt + (size_t)m_blk * KC * TILE_U32);
    // B fragment stream base for this warp: [kc][j][ks] addressing
    const uint32_t* Bg = g_Wt + (size_t)n_blk * KC * TILE_U32
                       + ((wn * 4) * 4 * 32 + lane) * 2;

    float acc[4][4][4];
#pragma unroll
    for (int i = 0; i < 4; i++)
#pragma unroll
        for (int j = 0; j < 4; j++)
#pragma unroll
            for (int r = 0; r < 4; r++) acc[i][j][r] = 0.0f;

    // prefetch A stages 0..STAGES-2 (4 x 16B per thread per tile)
#pragma unroll
    for (int c = 0; c < STAGES - 1; c++) {
#pragma unroll
        for (int i = 0; i < 4; i++)
            cp_async16(sA0 + c * TILE_BYTES + i * 4096 + tid * 16,
                       Ag + (size_t)c * TILE_BYTES + i * 4096 + tid * 16);
        cp_commit();
    }

    // B double buffer: preload (chunk 0, ks 0)
    uint32_t bcur[4][2], bnxt[4][2];
#pragma unroll
    for (int j = 0; j < 4; j++) {
        uint2 v = __ldg(reinterpret_cast<const uint2*>(Bg + j * 256));
        bnxt[j][0] = v.x; bnxt[j][1] = v.y;
    }

    for (int c = 0; c < KC; c++) {
        cp_wait<STAGES - 2>();
        __syncthreads();

        // prefetch A chunk c + STAGES - 1
        int cp = c + STAGES - 1;
        if (cp < KC) {
            int s = cp % STAGES;
#pragma unroll
            for (int i = 0; i < 4; i++)
                cp_async16(sA0 + s * TILE_BYTES + i * 4096 + tid * 16,
                           Ag + (size_t)cp * TILE_BYTES + i * 4096 + tid * 16);
        }
        cp_commit();

        const uint32_t* A = sA + (c % STAGES) * TILE_U32;

#pragma unroll
        for (int ks = 0; ks < 4; ks++) {
            // rotate B buffer; issue LDG for next ks (or next chunk's ks=0)
#pragma unroll
            for (int j = 0; j < 4; j++) {
                bcur[j][0] = bnxt[j][0];
                bcur[j][1] = bnxt[j][1];
            }
            {
                const uint32_t* Bn = (ks < 3)
                    ? (Bg + (size_t)c * TILE_U32 + (ks + 1) * 64)
                    : (Bg + (size_t)((c + 1 < KC) ? c + 1 : c) * TILE_U32);
#pragma unroll
                for (int j = 0; j < 4; j++) {
                    uint2 v = __ldg(reinterpret_cast<const uint2*>(Bn + j * 256));
                    bnxt[j][0] = v.x; bnxt[j][1] = v.y;
                }
            }

            uint32_t a[4][4];
#pragma unroll
            for (int i = 0; i < 4; i++) {
                uint4 v = *reinterpret_cast<const uint4*>(
                    A + (((wm * 4 + i) * 4 + ks) * 32 + lane) * 4);
                a[i][0] = v.x; a[i][1] = v.y; a[i][2] = v.z; a[i][3] = v.w;
            }
#pragma unroll
            for (int i = 0; i < 4; i++)
#pragma unroll
                for (int j = 0; j < 4; j++)
                    mma_f16(acc[i][j], a[i], bcur[j]);
        }
        __syncthreads();
    }

    // epilogue: c0,c1 at (row, col/col+1); c2,c3 at (row+8, ·)
    const int row0 = m_blk * BM + wm * 64 + (lane >> 2);
    const int col0 = n_blk * BN + wn * 32 + (lane & 3) * 2;
#pragma unroll
    for (int j = 0; j < 4; j++) {
        const int n = col0 + j * 8;
        const float2 bv = *reinterpret_cast<const float2*>(bias + n);
#pragma unroll
        for (int i = 0; i < 4; i++) {
            const int m = row0 + i * 16;
            float2 v0, v1;
            v0.x = acc[i][j][0] + bv.x;
            v0.y = acc[i][j][1] + bv.y;
            v1.x = acc[i][j][2] + bv.x;
            v1.y = acc[i][j][3] + bv.y;
            *reinterpret_cast<float2*>(out + (size_t)m * NFc + n)       = v0;
            *reinterpret_cast<float2*>(out + (size_t)(m + 8) * NFc + n) = v1;
        }
    }
}

// ---------------------------------------------------------------------------
// Launch
// ---------------------------------------------------------------------------
extern "C" void kernel_launch(void* const* d_in, const int* in_sizes, int n_in,
                              void* d_out, int out_size) {
    const float* x      = (const float*)d_in[0];
    const int*   binary = (const int*)  d_in[1];
    const float* scale  = (const float*)d_in[2];
    const float* bias   = (const float*)d_in[3];
    float*       out    = (float*)d_out;

    cudaFuncSetAttribute(gemm_kernel,
                         cudaFuncAttributeMaxDynamicSharedMemorySize, SMEM_TOTAL);

    prep_kernel<<<3072, 256>>>(binary, scale, x);

    dim3 grid(NFc / BN, Mc / BM);      // 32 x 32
    gemm_kernel<<<grid, 256, SMEM_TOTAL>>>(bias, out);
}

// round 11
// speedup vs baseline: 1.1792x; 1.1088x over previous
#include <cuda_runtime.h>
#include <cuda_fp16.h>
#include <cstdint>

// Problem constants (fixed by the dataset)
#define NXc   1024          // input features (K)
#define NFc   4096          // output features (N)
#define BITSc 8             // bit planes
#define Gc    128           // NX/8 packed groups
#define Mc    4096          // tokens (2*2048)

#define BM 128
#define BN 128
#define BK 64               // k per chunk (4 k-steps of 16)
#define KC (NXc / BK)       // 16 k-chunks
#define NSTEP (KC * 4)      // 64 flat (chunk, ks) steps

// Fragment-major fp16 tiles (uint32 = half2), 16KB each:
//   A tile: [mt(8)][ks(4)][lane(32)][4 regs]  = 4096 u32
//   B tile: [nt(16)][ks(4)][lane(32)][2 regs] = 4096 u32
#define TILE_U32   4096

__device__ uint32_t g_Xt[(size_t)Mc * NXc / 2];   // [m_blk(32)][kc(16)][TILE]
__device__ uint32_t g_Wt[(size_t)NFc * NXc / 2];  // [n_blk(32)][kc(16)][TILE]

// ---------------------------------------------------------------------------
__device__ __forceinline__ uint32_t pack_h2(float lo, float hi) {
    __half2 h = __floats2half2_rn(lo, hi);   // lo -> low 16 bits
    return *reinterpret_cast<uint32_t*>(&h);
}
__device__ __forceinline__ void mma_f16(float* d, const uint32_t* a, const uint32_t* b) {
    asm volatile(
        "mma.sync.aligned.m16n8k16.row.col.f32.f16.f16.f32 "
        "{%0,%1,%2,%3}, {%4,%5,%6,%7}, {%8,%9}, {%0,%1,%2,%3};"
        : "+f"(d[0]), "+f"(d[1]), "+f"(d[2]), "+f"(d[3])
        : "r"(a[0]), "r"(a[1]), "r"(a[2]), "r"(a[3]), "r"(b[0]), "r"(b[1]));
}

// ---------------------------------------------------------------------------
// Fused prep kernel: blocks [0,1024) decode W; blocks [1024,3072) repack x.
// Layouts identical to the proven R4 kernels.
// ---------------------------------------------------------------------------
__global__ void __launch_bounds__(256)
prep_kernel(const int* __restrict__ binary, const float* __restrict__ scale,
            const float* __restrict__ x) {
    if (blockIdx.x < 1024) {
        // ---- decode: packed signs -> W, fragment-major fp16 B layout ----
        int tid = blockIdx.x * 256 + threadIdx.x;   // NF * G/2 threads
        int f  = tid >> 6;
        int gp = tid & 63;

        float w[16];
#pragma unroll
        for (int j = 0; j < 16; j++) w[j] = 0.0f;
#pragma unroll
        for (int k = 0; k < BITSc; k++) {
            int2 bb = *reinterpret_cast<const int2*>(
                binary + (size_t)(k * NFc + f) * Gc + 2 * gp);
            float s = __ldg(scale + k * NFc + f);
#pragma unroll
            for (int j = 0; j < 8; j++) {
                w[j]     += ((bb.x >> (7 - j)) & 1) ? s : -s;
                w[8 + j] += ((bb.y >> (7 - j)) & 1) ? s : -s;
            }
        }

        int n_blk = f >> 7;
        int nt    = (f & 127) >> 3;
        int col   = f & 7;
        int kc    = gp >> 2;           // k-chunk (BK=64)
        int ks    = gp & 3;            // k16-step within chunk

        uint32_t* tile = g_Wt + (size_t)(n_blk * KC + kc) * TILE_U32;
        uint32_t* base = tile + ((nt * 4 + ks) * 32 + col * 4) * 2;
#pragma unroll
        for (int c = 0; c < 4; c++) {
            uint2 v;
            v.x = pack_h2(w[2 * c], w[2 * c + 1]);
            v.y = pack_h2(w[8 + 2 * c], w[9 + 2 * c]);
            *reinterpret_cast<uint2*>(base + c * 2) = v;
        }
    } else {
        // ---- repack: x -> fragment-major fp16 A layout ----
        int tid  = (blockIdx.x - 1024) * 256 + threadIdx.x;  // M*K/8 threads
        int lane = tid & 31;
        int ks   = (tid >> 5) & 3;
        int mt   = (tid >> 7) & 7;
        int kc   = (tid >> 10) & (KC - 1);
        int mblk = tid >> 14;

        int row = mblk * BM + mt * 16 + (lane >> 2);
        int k0  = kc * BK + ks * 16 + (lane & 3) * 2;

        const float* r0 = x + (size_t)row * NXc;
        const float* r1 = r0 + 8 * NXc;

        float2 p00 = *reinterpret_cast<const float2*>(r0 + k0);
        float2 p10 = *reinterpret_cast<const float2*>(r1 + k0);
        float2 p01 = *reinterpret_cast<const float2*>(r0 + k0 + 8);
        float2 p11 = *reinterpret_cast<const float2*>(r1 + k0 + 8);

        uint4 v;
        v.x = pack_h2(p00.x, p00.y);
        v.y = pack_h2(p10.x, p10.y);
        v.z = pack_h2(p01.x, p01.y);
        v.w = pack_h2(p11.x, p11.y);

        uint32_t* tile = g_Xt + (size_t)(mblk * KC + kc) * TILE_U32;
        *reinterpret_cast<uint4*>(tile + ((mt * 4 + ks) * 32 + lane) * 4) = v;
    }
}

// ---------------------------------------------------------------------------
// GEMM: barrier-free, smem-free fp16 mma.sync. 128x128 CTA tile, 256 threads
// (8 warps, 2m x 4n, warp tile 64x32). Both operands stream via LDG from the
// fragment-major global layouts into double-buffered register fragments —
// no cp.async, no STS/LDS, no __syncthreads: each warp free-runs, so tensor
// pipes stay fed instead of stalling at chunk-boundary rendezvous.
// ---------------------------------------------------------------------------
__global__ void __launch_bounds__(256, 2)
gemm_kernel(const float* __restrict__ bias, float* __restrict__ out) {
    const int tid  = threadIdx.x;
    const int lane = tid & 31;
    const int wid  = tid >> 5;
    const int wm   = wid >> 2;      // 0..1
    const int wn   = wid & 3;       // 0..3
    const int n_blk = blockIdx.x;
    const int m_blk = blockIdx.y;

    // warp-private fragment stream bases
    // A frag (i, step s): Aw + (s>>2)*4096 + (s&3)*128 + i*512   (uint4)
    // B frag (j, step s): Bw + (s>>2)*4096 + (s&3)*64  + j*256   (uint2)
    const uint32_t* Aw = g_Xt + (size_t)m_blk * KC * TILE_U32
                       + ((wm * 4) * 4 * 32 + lane) * 4;
    const uint32_t* Bw = g_Wt + (size_t)n_blk * KC * TILE_U32
                       + ((wn * 4) * 4 * 32 + lane) * 2;

    float acc[4][4][4];
#pragma unroll
    for (int i = 0; i < 4; i++)
#pragma unroll
        for (int j = 0; j < 4; j++)
#pragma unroll
            for (int r = 0; r < 4; r++) acc[i][j][r] = 0.0f;

    uint32_t a[2][4][4], b[2][4][2];

    // preload step 0
#pragma unroll
    for (int i = 0; i < 4; i++) {
        uint4 v = __ldg(reinterpret_cast<const uint4*>(Aw + i * 512));
        a[0][i][0] = v.x; a[0][i][1] = v.y; a[0][i][2] = v.z; a[0][i][3] = v.w;
    }
#pragma unroll
    for (int j = 0; j < 4; j++) {
        uint2 v = __ldg(reinterpret_cast<const uint2*>(Bw + j * 256));
        b[0][j][0] = v.x; b[0][j][1] = v.y;
    }

#pragma unroll 4
    for (int s = 0; s < NSTEP; s++) {
        const int cur = s & 1, nxt = cur ^ 1;

        // prefetch step s+1 (overlaps this step's 16 MMAs)
        if (s < NSTEP - 1) {
            const int sn   = s + 1;
            const int offA = (sn >> 2) * 4096 + (sn & 3) * 128;
            const int offB = (sn >> 2) * 4096 + (sn & 3) * 64;
#pragma unroll
            for (int i = 0; i < 4; i++) {
                uint4 v = __ldg(reinterpret_cast<const uint4*>(Aw + offA + i * 512));
                a[nxt][i][0] = v.x; a[nxt][i][1] = v.y;
                a[nxt][i][2] = v.z; a[nxt][i][3] = v.w;
            }
#pragma unroll
            for (int j = 0; j < 4; j++) {
                uint2 v = __ldg(reinterpret_cast<const uint2*>(Bw + offB + j * 256));
                b[nxt][j][0] = v.x; b[nxt][j][1] = v.y;
            }
        }

#pragma unroll
        for (int i = 0; i < 4; i++)
#pragma unroll
            for (int j = 0; j < 4; j++)
                mma_f16(acc[i][j], a[cur][i], b[cur][j]);
    }

    // epilogue: c0,c1 at (row, col/col+1); c2,c3 at (row+8, ·)
    const int row0 = m_blk * BM + wm * 64 + (lane >> 2);
    const int col0 = n_blk * BN + wn * 32 + (lane & 3) * 2;
#pragma unroll
    for (int j = 0; j < 4; j++) {
        const int n = col0 + j * 8;
        const float2 bv = *reinterpret_cast<const float2*>(bias + n);
#pragma unroll
        for (int i = 0; i < 4; i++) {
            const int m = row0 + i * 16;
            float2 v0, v1;
            v0.x = acc[i][j][0] + bv.x;
            v0.y = acc[i][j][1] + bv.y;
            v1.x = acc[i][j][2] + bv.x;
            v1.y = acc[i][j][3] + bv.y;
            *reinterpret_cast<float2*>(out + (size_t)m * NFc + n)       = v0;
            *reinterpret_cast<float2*>(out + (size_t)(m + 8) * NFc + n) = v1;
        }
    }
}

// ---------------------------------------------------------------------------
// Launch
// ---------------------------------------------------------------------------
extern "C" void kernel_launch(void* const* d_in, const int* in_sizes, int n_in,
                              void* d_out, int out_size) {
    const float* x      = (const float*)d_in[0];
    const int*   binary = (const int*)  d_in[1];
    const float* scale  = (const float*)d_in[2];
    const float* bias   = (const float*)d_in[3];
    float*       out    = (float*)d_out;

    prep_kernel<<<3072, 256>>>(binary, scale, x);

    dim3 grid(NFc / BN, Mc / BM);      // 32 x 32
    gemm_kernel<<<grid, 256>>>(bias, out);
}